// round 17
// baseline (speedup 1.0000x reference)
#include <cuda_runtime.h>

#define FULL 0xffffffffu

// LISTA v12 = R5 (confirmed champion, deterministic 8.672us) + pure chain
// trims with ZERO prolog cost (R9 showed trims + 12KB W2 staging = net loss;
// keep W2 as hoisted unrolled LDGs):
//  1. sign via single fma combine (a = a0 + sgn*a1), not 4 on-chain muls
//  2. 3-op soft threshold  v - min(max(v,-t),t)
//  3. conv2 edge zeroing folded into weights (off-chain SELs)
//  4. conv2 with 3 accumulators
// lane = h*16 + c*8 + i; warp = one column; 16 blocks x 128 threads.

__global__ void __launch_bounds__(128, 1) lista_kernel(
    const float* __restrict__ y_real, const float* __restrict__ y_imag,
    const float* __restrict__ w1_real, const float* __restrict__ w1_imag,
    const float* __restrict__ w2_real, const float* __restrict__ w2_imag,
    const float* __restrict__ thr,
    const float* __restrict__ c1w, const float* __restrict__ c1b,
    const float* __restrict__ c2w, const float* __restrict__ c2b,
    float* __restrict__ out)
{
    // conv params staged into shared, padded + aligned for LDS.128
    __shared__ __align__(16) float s_c1w[16 * 12];   // 9 used + 3 pad per stage
    __shared__ __align__(16) float s_c1b[16 * 4];    // 3 used + 1 pad
    __shared__ __align__(16) float s_c2w[16 * 12];
    __shared__ __align__(16) float s_misc[16 * 2];   // {c2b[s], thr[s]}

    const int tid  = threadIdx.x;          // 0..127
    const int lane = tid & 31;
    const int i    = lane & 7;
    const int c    = (lane >> 3) & 1;
    const int h    = lane >> 4;
    const int b    = (int)blockIdx.x * 4 + (tid >> 5);   // batch column
    const float sgn = c ? 1.f : -1.f;   // zr uses -w_i*x_i ; zi uses +w_i*x_r

    // ---- one-time staging of conv params (small; padded, aligned) ----
    for (int k = tid; k < 192; k += 128) {
        int s = k / 12, r = k - s * 12;
        s_c1w[k] = (r < 9) ? c1w[s * 9 + r] : 0.f;
        s_c2w[k] = (r < 9) ? c2w[s * 9 + r] : 0.f;
    }
    if (tid < 64) {
        int s = tid >> 2, r = tid & 3;
        s_c1b[tid] = (r < 3) ? c1b[s * 3 + r] : 0.f;
    }
    if (tid < 32) {
        int s = tid >> 1;
        s_misc[tid] = (tid & 1) ? thr[s] : c2b[s];
    }

    // ---- y slice for this thread's j-half (own comp + signed opposite) ----
    float yc[4], yos[4];
    {
        const float* yc_ptr = c ? y_imag : y_real;
        const float* yo_ptr = c ? y_real : y_imag;
        #pragma unroll
        for (int j4 = 0; j4 < 4; j4++) {
            int j = h * 4 + j4;
            yc[j4]  = yc_ptr[j * 64 + b];
            yos[j4] = sgn * yo_ptr[j * 64 + b];
        }
    }

    // ---- precompute all 16 stage HALF-biases (W1[s] y)_{i,c}, this j-half.
    float bias[16];
    #pragma unroll
    for (int s = 0; s < 16; s++) {
        const float4 wr = *(const float4*)(w1_real + s * 64 + i * 8 + h * 4);
        const float4 wi = *(const float4*)(w1_imag + s * 64 + i * 8 + h * 4);
        float a = 0.f;
        a = fmaf(wr.x, yc[0], a); a = fmaf(wi.x, yos[0], a);
        a = fmaf(wr.y, yc[1], a); a = fmaf(wi.y, yos[1], a);
        a = fmaf(wr.z, yc[2], a); a = fmaf(wi.z, yos[2], a);
        a = fmaf(wr.w, yc[3], a); a = fmaf(wi.w, yos[3], a);
        bias[s] = a;                       // half-sum only
    }

    __syncthreads();

    // ---- init: x = soft(full bias[0], thr[0]) ----
    float x;
    {
        const float b0 = bias[0] + __shfl_xor_sync(FULL, bias[0], 16);
        const float t0 = s_misc[1];
        x = b0 - fminf(fmaxf(b0, -t0), t0);
    }

    const int src_c = (c << 3);        // lanes holding own-comp x_j
    const int src_o = ((c ^ 1) << 3);  // lanes holding opposite-comp x_j
    const int nbase = lane & 24;       // keep (c,h) bits for neighbor shfl
    const bool  e0 = (i > 0), e2 = (i < 7);

    // ---- 16 sequential stages (fully unrolled) ----
    #pragma unroll
    for (int s = 0; s < 16; s++) {
        // broadcast x for this thread's j-half (raw values; sign applied
        // once in the combine fma below, NOT per-element)
        float xc[4], xo[4];
        #pragma unroll
        for (int j4 = 0; j4 < 4; j4++) {
            int j = h * 4 + j4;
            xc[j4] = __shfl_sync(FULL, x, src_c + j);
            xo[j4] = __shfl_sync(FULL, x, src_o + j);
        }

        // half dot: two parallel 4-fma chains, single sgn combine
        const float4 wr = *(const float4*)(w2_real + s * 64 + i * 8 + h * 4);
        const float4 wi = *(const float4*)(w2_imag + s * 64 + i * 8 + h * 4);
        float a0 = bias[s], a1 = 0.f;
        a0 = fmaf(wr.x, xc[0], a0); a1 = fmaf(wi.x, xo[0], a1);
        a0 = fmaf(wr.y, xc[1], a0); a1 = fmaf(wi.y, xo[1], a1);
        a0 = fmaf(wr.z, xc[2], a0); a1 = fmaf(wi.z, xo[2], a1);
        a0 = fmaf(wr.w, xc[3], a0); a1 = fmaf(wi.w, xo[3], a1);
        const float a = fmaf(sgn, a1, a0);
        const float z = a + __shfl_xor_sync(FULL, a, 16);  // full bias+dot

        // z neighbors at +-1, +-2 (same component, zero-padded via SEL)
        float zv[5];
        zv[2] = z;
        float zm2 = __shfl_sync(FULL, z, nbase | ((i - 2) & 7));
        float zm1 = __shfl_sync(FULL, z, nbase | ((i - 1) & 7));
        float zp1 = __shfl_sync(FULL, z, nbase | ((i + 1) & 7));
        float zp2 = __shfl_sync(FULL, z, nbase | ((i + 2) & 7));
        zv[0] = (i >= 2) ? zm2 : 0.f;
        zv[1] = (i >= 1) ? zm1 : 0.f;
        zv[3] = (i <= 6) ? zp1 : 0.f;
        zv[4] = (i <= 5) ? zp2 : 0.f;

        // conv params (shared, broadcast LDS.128 — hoistable)
        const float4 wa  = *(const float4*)(s_c1w + s * 12);
        const float4 wb  = *(const float4*)(s_c1w + s * 12 + 4);
        const float4 wcv = *(const float4*)(s_c1w + s * 12 + 8);
        const float4 b1  = *(const float4*)(s_c1b + s * 4);
        const float4 va  = *(const float4*)(s_c2w + s * 12);
        const float4 vb  = *(const float4*)(s_c2w + s * 12 + 4);
        const float4 vc  = *(const float4*)(s_c2w + s * 12 + 8);
        const float  cb2 = s_misc[s * 2];
        const float  t   = s_misc[s * 2 + 1];
        const float  tn  = -t;

        const float k1[3][3] = {{wa.x, wa.y, wa.z},
                                {wa.w, wb.x, wb.y},
                                {wb.z, wb.w, wcv.x}};
        const float bb1[3] = {b1.x, b1.y, b1.z};
        // k2 row-major [ch][pos]; edge taps zeroed OFF the z-dependent chain
        const float k2m[3][3] = {{e0 ? va.x : 0.f, va.y, e2 ? va.z : 0.f},
                                 {e0 ? va.w : 0.f, vb.x, e2 ? vb.y : 0.f},
                                 {e0 ? vb.z : 0.f, vb.w, e2 ? vc.x : 0.f}};

        // conv1 + 3-op soft at pos i-1, i, i+1; conv2 with 3 accumulators
        float o0 = cb2, o1 = 0.f, o2 = 0.f;
        #pragma unroll
        for (int ch = 0; ch < 3; ch++) {
            const float w0 = k1[ch][0], w1 = k1[ch][1], w2 = k1[ch][2];
            const float bb = bb1[ch];
            float v0 = bb, v1 = bb, v2 = bb;
            v0 = fmaf(w0, zv[0], v0); v1 = fmaf(w0, zv[1], v1); v2 = fmaf(w0, zv[2], v2);
            v0 = fmaf(w1, zv[1], v0); v1 = fmaf(w1, zv[2], v1); v2 = fmaf(w1, zv[3], v2);
            v0 = fmaf(w2, zv[2], v0); v1 = fmaf(w2, zv[3], v1); v2 = fmaf(w2, zv[4], v2);
            const float s0 = v0 - fminf(fmaxf(v0, tn), t);
            const float s1 = v1 - fminf(fmaxf(v1, tn), t);
            const float s2 = v2 - fminf(fmaxf(v2, tn), t);
            o0 = fmaf(k2m[ch][0], s0, o0);
            o1 = fmaf(k2m[ch][1], s1, o1);
            o2 = fmaf(k2m[ch][2], s2, o2);
        }
        x = (o0 + o1) + o2;
    }

    // out: x_r (8,64) then x_i (8,64); h=0 lanes write
    if (h == 0) out[c * 512 + i * 64 + b] = x;
}

extern "C" void kernel_launch(void* const* d_in, const int* in_sizes, int n_in,
                              void* d_out, int out_size) {
    (void)in_sizes; (void)n_in; (void)out_size;
    const float* y_real  = (const float*)d_in[0];
    const float* y_imag  = (const float*)d_in[1];
    const float* w1_real = (const float*)d_in[2];
    const float* w1_imag = (const float*)d_in[3];
    const float* w2_real = (const float*)d_in[4];
    const float* w2_imag = (const float*)d_in[5];
    const float* thr     = (const float*)d_in[6];
    const float* c1w     = (const float*)d_in[7];
    const float* c1b     = (const float*)d_in[8];
    const float* c2w     = (const float*)d_in[9];
    const float* c2b     = (const float*)d_in[10];
    float* out = (float*)d_out;

    lista_kernel<<<16, 128>>>(y_real, y_imag, w1_real, w1_imag,
                              w2_real, w2_imag, thr, c1w, c1b, c2w, c2b, out);
}